// round 1
// baseline (speedup 1.0000x reference)
#include <cuda_runtime.h>
#include <cuda_bf16.h>
#include <stdint.h>

#define N_NODES 50000
#define N_EDGES 1000000
#define IN_SIZE 256
#define OUT_SIZE 128
#define N_ET 3

// Scratch: per-etype projected features and in-degree (float).
__device__ float g_Wh[(size_t)N_ET * N_NODES * OUT_SIZE];   // 76.8 MB
__device__ float g_deg[N_ET * N_NODES];

// ---------------------------------------------------------------------------
// Stage 0: zero the degree array (must be re-zeroed every launch: determinism)
// ---------------------------------------------------------------------------
__global__ void zero_deg_kernel() {
    int i = blockIdx.x * blockDim.x + threadIdx.x;
    if (i < N_ET * N_NODES) g_deg[i] = 0.0f;
}

// ---------------------------------------------------------------------------
// Stage 1: Wh[e] = x @ W[e]   (bias deferred to normalize stage)
// Tiled SGEMM: BM=64, BN=128(=OUT), BK=16; 256 threads; 8x4 accum per thread.
// ---------------------------------------------------------------------------
#define BM 64
#define BK 16

__global__ __launch_bounds__(256) void gemm_kernel(const float* __restrict__ x,
                                                   const float* __restrict__ W) {
    const int et = blockIdx.y;
    const int m0 = blockIdx.x * BM;
    __shared__ float xs[BK][BM + 1];       // +1 pad: avoid store bank conflicts
    __shared__ float ws[BK][OUT_SIZE];

    const float* Wt = W + (size_t)et * IN_SIZE * OUT_SIZE;
    const int tid = threadIdx.x;
    const int ty = tid >> 5;               // 0..7  (row group of 8)
    const int tx = tid & 31;               // 0..31 (col group of 4)

    float acc[8][4];
#pragma unroll
    for (int i = 0; i < 8; i++)
#pragma unroll
        for (int j = 0; j < 4; j++) acc[i][j] = 0.0f;

    for (int k0 = 0; k0 < IN_SIZE; k0 += BK) {
        // load x tile (BM x BK = 1024 elems, 4 per thread)
#pragma unroll
        for (int i = 0; i < 4; i++) {
            int idx = tid + i * 256;
            int row = idx / BK;
            int col = idx % BK;
            int gm = m0 + row;
            float v = 0.0f;
            if (gm < N_NODES) v = x[(size_t)gm * IN_SIZE + k0 + col];
            xs[col][row] = v;
        }
        // load W tile (BK x 128 = 2048 elems, 8 per thread), coalesced
#pragma unroll
        for (int i = 0; i < 8; i++) {
            int idx = tid + i * 256;
            int r = idx >> 7;              // /128
            int c = idx & 127;
            ws[r][c] = Wt[(size_t)(k0 + r) * OUT_SIZE + c];
        }
        __syncthreads();

#pragma unroll
        for (int k = 0; k < BK; k++) {
            float4 b4 = *(const float4*)&ws[k][tx * 4];
            float a[8];
#pragma unroll
            for (int i = 0; i < 8; i++) a[i] = xs[k][ty * 8 + i];
#pragma unroll
            for (int i = 0; i < 8; i++) {
                acc[i][0] += a[i] * b4.x;
                acc[i][1] += a[i] * b4.y;
                acc[i][2] += a[i] * b4.z;
                acc[i][3] += a[i] * b4.w;
            }
        }
        __syncthreads();
    }

    float* dst = g_Wh + (size_t)et * N_NODES * OUT_SIZE;
#pragma unroll
    for (int i = 0; i < 8; i++) {
        int gm = m0 + ty * 8 + i;
        if (gm < N_NODES) {
            float4 v = make_float4(acc[i][0], acc[i][1], acc[i][2], acc[i][3]);
            *(float4*)&dst[(size_t)gm * OUT_SIZE + tx * 4] = v;
        }
    }
}

// ---------------------------------------------------------------------------
// Stage 2: edge scatter-add.  One warp per edge; lane handles 4 contiguous
// output channels (float4 gather from Wh[src], 4 atomicAdds to out[dst]).
// out layout: [node][etype][128] (matches required [N, E_types, OUT]).
// ---------------------------------------------------------------------------
__global__ __launch_bounds__(256) void scatter_kernel(const int* __restrict__ esrc,
                                                      const int* __restrict__ edst,
                                                      float* __restrict__ out) {
    const int et = blockIdx.y;
    const int edge = (blockIdx.x * blockDim.x + threadIdx.x) >> 5;
    const int lane = threadIdx.x & 31;
    if (edge >= N_EDGES) return;

    const int src = esrc[(size_t)et * N_EDGES + edge];
    const int dst = edst[(size_t)et * N_EDGES + edge];

    const float4 v = *(const float4*)&g_Wh[((size_t)et * N_NODES + src) * OUT_SIZE + lane * 4];
    float* o = out + (size_t)dst * (N_ET * OUT_SIZE) + et * OUT_SIZE + lane * 4;
    atomicAdd(o + 0, v.x);
    atomicAdd(o + 1, v.y);
    atomicAdd(o + 2, v.z);
    atomicAdd(o + 3, v.w);
    if (lane == 0) atomicAdd(&g_deg[et * N_NODES + dst], 1.0f);
}

// ---------------------------------------------------------------------------
// Stage 3: normalize (mean) + bias, in place on d_out.
// out[n,et,c] = deg>0 ? sum/deg + b[et,c] : 0
// ---------------------------------------------------------------------------
__global__ __launch_bounds__(256) void normalize_kernel(float* __restrict__ out,
                                                        const float* __restrict__ b) {
    size_t i = (size_t)blockIdx.x * blockDim.x + threadIdx.x;
    const size_t total = (size_t)N_NODES * N_ET * OUT_SIZE;
    if (i >= total) return;
    int c = (int)(i & (OUT_SIZE - 1));
    int et = (int)((i >> 7) % N_ET);
    int n = (int)(i / (OUT_SIZE * N_ET));
    float d = g_deg[et * N_NODES + n];
    float s = out[i];
    out[i] = (d > 0.0f) ? (s / d + b[et * OUT_SIZE + c]) : 0.0f;
}

// ---------------------------------------------------------------------------
extern "C" void kernel_launch(void* const* d_in, const int* in_sizes, int n_in,
                              void* d_out, int out_size) {
    const float* x    = (const float*)d_in[0];
    const int*   esrc = (const int*)d_in[1];
    const int*   edst = (const int*)d_in[2];
    const float* W    = (const float*)d_in[3];
    const float* b    = (const float*)d_in[4];
    float* out = (float*)d_out;

    // Zero accumulators (every call; graph-capturable async ops on stream 0).
    cudaMemsetAsync(d_out, 0, (size_t)out_size * sizeof(float), 0);
    zero_deg_kernel<<<(N_ET * N_NODES + 255) / 256, 256>>>();

    // GEMM: grid (node tiles, etypes)
    dim3 ggrid((N_NODES + BM - 1) / BM, N_ET);
    gemm_kernel<<<ggrid, 256>>>(x, W);

    // Scatter: 8 edges per 256-thread block (1 warp/edge)
    dim3 sgrid((N_EDGES + 7) / 8, N_ET);
    scatter_kernel<<<sgrid, 256>>>(esrc, edst, out);

    // Normalize + bias
    size_t total = (size_t)N_NODES * N_ET * OUT_SIZE;
    normalize_kernel<<<(unsigned)((total + 255) / 256), 256>>>(out, b);
}

// round 2
// speedup vs baseline: 1.6135x; 1.6135x over previous
#include <cuda_runtime.h>
#include <cuda_bf16.h>
#include <stdint.h>

#define N_NODES 50000
#define N_EDGES 1000000
#define IN_SIZE 256
#define OUT_SIZE 128
#define N_ET 3

// Scratch: per-etype projected features and in-degree (float).
__device__ float g_Wh[(size_t)N_ET * N_NODES * OUT_SIZE];   // 76.8 MB
__device__ float g_deg[N_ET * N_NODES];

__global__ void zero_deg_kernel() {
    int i = blockIdx.x * blockDim.x + threadIdx.x;
    if (i < N_ET * N_NODES) g_deg[i] = 0.0f;
}

// ---------------------------------------------------------------------------
// Stage 1: Wh[e] = x @ W[e] via 3xTF32 mma.sync (fp32-accurate tensor GEMM).
// Tile: BM=128, BN=128, BK=16. 8 warps; warp tile 32x64 (2 m-frags x 8 n-frags).
// ---------------------------------------------------------------------------
__device__ __forceinline__ float tf32_rna(float x) {
    uint32_t u;
    asm("cvt.rna.tf32.f32 %0, %1;" : "=r"(u) : "f"(x));
    return __uint_as_float(u);
}

#define MMA_TF32(D, A, B)                                                     \
    asm volatile(                                                             \
        "mma.sync.aligned.m16n8k8.row.col.f32.tf32.tf32.f32 "                 \
        "{%0,%1,%2,%3}, {%4,%5,%6,%7}, {%8,%9}, {%0,%1,%2,%3};"               \
        : "+f"(D[0]), "+f"(D[1]), "+f"(D[2]), "+f"(D[3])                      \
        : "r"(A[0]), "r"(A[1]), "r"(A[2]), "r"(A[3]), "r"(B[0]), "r"(B[1]))

#define AS_STRIDE 20   // 16 k + 4 pad -> conflict-free frag loads

__global__ __launch_bounds__(256, 1) void gemm_kernel(const float* __restrict__ x,
                                                      const float* __restrict__ W) {
    const int et = blockIdx.y;
    const int m0 = blockIdx.x * 128;
    const int tid = threadIdx.x;
    const int wid = tid >> 5;
    const int lane = tid & 31;
    const int m_off = (wid >> 1) * 32;   // warp M offset (0,32,64,96)
    const int n_off = (wid & 1) * 64;    // warp N offset (0,64)
    const int gq = lane >> 2;            // groupID
    const int tg = lane & 3;             // thread-in-group

    __shared__ float As_hi[128 * AS_STRIDE];
    __shared__ float As_lo[128 * AS_STRIDE];
    __shared__ float Ws_hi[128 * AS_STRIDE];   // [n][k]
    __shared__ float Ws_lo[128 * AS_STRIDE];

    const float* Wt = W + (size_t)et * IN_SIZE * OUT_SIZE;

    float acc[2][8][4];
#pragma unroll
    for (int i = 0; i < 2; i++)
#pragma unroll
        for (int j = 0; j < 8; j++)
#pragma unroll
            for (int c = 0; c < 4; c++) acc[i][j][c] = 0.0f;

    for (int k0 = 0; k0 < IN_SIZE; k0 += 16) {
        // -- load x tile (128 rows x 16 k), split hi/lo
#pragma unroll
        for (int i = 0; i < 2; i++) {
            int f4 = tid + i * 256;          // 0..511
            int row = f4 >> 2;               // 0..127
            int kc = (f4 & 3) * 4;
            int gm = m0 + row;
            float4 v = make_float4(0.f, 0.f, 0.f, 0.f);
            if (gm < N_NODES) v = *(const float4*)&x[(size_t)gm * IN_SIZE + k0 + kc];
            float4 h, l;
            h.x = tf32_rna(v.x); l.x = tf32_rna(v.x - h.x);
            h.y = tf32_rna(v.y); l.y = tf32_rna(v.y - h.y);
            h.z = tf32_rna(v.z); l.z = tf32_rna(v.z - h.z);
            h.w = tf32_rna(v.w); l.w = tf32_rna(v.w - h.w);
            *(float4*)&As_hi[row * AS_STRIDE + kc] = h;
            *(float4*)&As_lo[row * AS_STRIDE + kc] = l;
        }
        // -- load W tile (16 k x 128 n), transposed into [n][k], split hi/lo
#pragma unroll
        for (int i = 0; i < 2; i++) {
            int f4 = tid + i * 256;
            int kr = f4 >> 5;                // 0..15
            int nc = (f4 & 31) * 4;
            float4 v = *(const float4*)&Wt[(size_t)(k0 + kr) * OUT_SIZE + nc];
            float h, l;
            h = tf32_rna(v.x); l = tf32_rna(v.x - h);
            Ws_hi[(nc + 0) * AS_STRIDE + kr] = h; Ws_lo[(nc + 0) * AS_STRIDE + kr] = l;
            h = tf32_rna(v.y); l = tf32_rna(v.y - h);
            Ws_hi[(nc + 1) * AS_STRIDE + kr] = h; Ws_lo[(nc + 1) * AS_STRIDE + kr] = l;
            h = tf32_rna(v.z); l = tf32_rna(v.z - h);
            Ws_hi[(nc + 2) * AS_STRIDE + kr] = h; Ws_lo[(nc + 2) * AS_STRIDE + kr] = l;
            h = tf32_rna(v.w); l = tf32_rna(v.w - h);
            Ws_hi[(nc + 3) * AS_STRIDE + kr] = h; Ws_lo[(nc + 3) * AS_STRIDE + kr] = l;
        }
        __syncthreads();

#pragma unroll
        for (int ks = 0; ks < 16; ks += 8) {
            uint32_t ahi[2][4], alo[2][4];
#pragma unroll
            for (int mf = 0; mf < 2; mf++) {
                int r = m_off + mf * 16 + gq;
                int c = ks + tg;
                ahi[mf][0] = __float_as_uint(As_hi[r * AS_STRIDE + c]);
                ahi[mf][1] = __float_as_uint(As_hi[(r + 8) * AS_STRIDE + c]);
                ahi[mf][2] = __float_as_uint(As_hi[r * AS_STRIDE + c + 4]);
                ahi[mf][3] = __float_as_uint(As_hi[(r + 8) * AS_STRIDE + c + 4]);
                alo[mf][0] = __float_as_uint(As_lo[r * AS_STRIDE + c]);
                alo[mf][1] = __float_as_uint(As_lo[(r + 8) * AS_STRIDE + c]);
                alo[mf][2] = __float_as_uint(As_lo[r * AS_STRIDE + c + 4]);
                alo[mf][3] = __float_as_uint(As_lo[(r + 8) * AS_STRIDE + c + 4]);
            }
#pragma unroll
            for (int nf = 0; nf < 8; nf++) {
                uint32_t bhi[2], blo[2];
                int n = n_off + nf * 8 + gq;
                int c = ks + tg;
                bhi[0] = __float_as_uint(Ws_hi[n * AS_STRIDE + c]);
                bhi[1] = __float_as_uint(Ws_hi[n * AS_STRIDE + c + 4]);
                blo[0] = __float_as_uint(Ws_lo[n * AS_STRIDE + c]);
                blo[1] = __float_as_uint(Ws_lo[n * AS_STRIDE + c + 4]);
#pragma unroll
                for (int mf = 0; mf < 2; mf++) {
                    MMA_TF32(acc[mf][nf], ahi[mf], bhi);
                    MMA_TF32(acc[mf][nf], ahi[mf], blo);
                    MMA_TF32(acc[mf][nf], alo[mf], bhi);
                }
            }
        }
        __syncthreads();
    }

    // epilogue: write Wh
    float* dst = g_Wh + (size_t)et * N_NODES * OUT_SIZE;
#pragma unroll
    for (int mf = 0; mf < 2; mf++) {
#pragma unroll
        for (int nf = 0; nf < 8; nf++) {
            int row = m0 + m_off + mf * 16 + gq;
            int col = n_off + nf * 8 + tg * 2;
            if (row < N_NODES) {
                *(float2*)&dst[(size_t)row * OUT_SIZE + col] =
                    make_float2(acc[mf][nf][0], acc[mf][nf][1]);
            }
            if (row + 8 < N_NODES) {
                *(float2*)&dst[(size_t)(row + 8) * OUT_SIZE + col] =
                    make_float2(acc[mf][nf][2], acc[mf][nf][3]);
            }
        }
    }
}

// ---------------------------------------------------------------------------
// Stage 2: edge scatter-add with vector reductions (red.global.add.v4.f32).
// One warp per edge; each lane handles 4 contiguous channels -> 1 RED.128.
// ---------------------------------------------------------------------------
__global__ __launch_bounds__(256) void scatter_kernel(const int* __restrict__ esrc,
                                                      const int* __restrict__ edst,
                                                      float* __restrict__ out) {
    const int et = blockIdx.y;
    const int edge = (blockIdx.x * blockDim.x + threadIdx.x) >> 5;
    const int lane = threadIdx.x & 31;
    if (edge >= N_EDGES) return;

    const int src = __ldg(&esrc[(size_t)et * N_EDGES + edge]);
    const int dst = __ldg(&edst[(size_t)et * N_EDGES + edge]);

    const float4 v = *(const float4*)&g_Wh[((size_t)et * N_NODES + src) * OUT_SIZE + lane * 4];
    float* o = out + (size_t)dst * (N_ET * OUT_SIZE) + et * OUT_SIZE + lane * 4;
    asm volatile("red.global.add.v4.f32 [%0], {%1,%2,%3,%4};"
                 :: "l"(o), "f"(v.x), "f"(v.y), "f"(v.z), "f"(v.w)
                 : "memory");
    if (lane == 0) atomicAdd(&g_deg[et * N_NODES + dst], 1.0f);
}

// ---------------------------------------------------------------------------
// Stage 3: normalize (mean) + bias, vectorized float4.
// ---------------------------------------------------------------------------
__global__ __launch_bounds__(256) void normalize_kernel(float* __restrict__ out,
                                                        const float* __restrict__ b) {
    size_t t = (size_t)blockIdx.x * blockDim.x + threadIdx.x;
    const size_t total = (size_t)N_NODES * N_ET * 32;   // float4 units
    if (t >= total) return;
    int c4 = (int)(t & 31);
    int et = (int)((t >> 5) % N_ET);
    int n = (int)(t / (32 * N_ET));
    float d = g_deg[et * N_NODES + n];
    float4 s = ((float4*)out)[t];
    if (d > 0.0f) {
        float inv = 1.0f / d;
        float4 bb = __ldg(&((const float4*)b)[et * 32 + c4]);
        s.x = s.x * inv + bb.x;
        s.y = s.y * inv + bb.y;
        s.z = s.z * inv + bb.z;
        s.w = s.w * inv + bb.w;
    } else {
        s = make_float4(0.f, 0.f, 0.f, 0.f);
    }
    ((float4*)out)[t] = s;
}

// ---------------------------------------------------------------------------
extern "C" void kernel_launch(void* const* d_in, const int* in_sizes, int n_in,
                              void* d_out, int out_size) {
    const float* x    = (const float*)d_in[0];
    const int*   esrc = (const int*)d_in[1];
    const int*   edst = (const int*)d_in[2];
    const float* W    = (const float*)d_in[3];
    const float* b    = (const float*)d_in[4];
    float* out = (float*)d_out;

    cudaMemsetAsync(d_out, 0, (size_t)out_size * sizeof(float), 0);
    zero_deg_kernel<<<(N_ET * N_NODES + 255) / 256, 256>>>();

    dim3 ggrid((N_NODES + 127) / 128, N_ET);
    gemm_kernel<<<ggrid, 256>>>(x, W);

    dim3 sgrid((N_EDGES + 7) / 8, N_ET);
    scatter_kernel<<<sgrid, 256>>>(esrc, edst, out);

    size_t total4 = (size_t)N_NODES * N_ET * 32;
    normalize_kernel<<<(unsigned)((total4 + 255) / 256), 256>>>(out, b);
}

// round 3
// speedup vs baseline: 2.2965x; 1.4233x over previous
#include <cuda_runtime.h>
#include <cuda_bf16.h>
#include <stdint.h>

#define N_NODES 50000
#define N_EDGES 1000000
#define IN_SIZE 256
#define OUT_SIZE 128
#define N_ET 3
#define N_TOT (N_ET * N_NODES)          // 150000
#define TOTAL_E (N_ET * N_EDGES)        // 3000000
#define SCAN_CHUNK 2048
#define SCAN_BLOCKS ((N_TOT + SCAN_CHUNK - 1) / SCAN_CHUNK)   // 74

// Scratch
__device__ float g_Wh[(size_t)N_ET * N_NODES * OUT_SIZE];     // 76.8 MB
__device__ int   g_cnt[N_TOT];
__device__ int   g_off[N_TOT + 1];
__device__ int   g_pos[N_TOT];
__device__ int   g_part[SCAN_BLOCKS];
__device__ int   g_eidx[TOTAL_E];       // src node per edge, dst-sorted

// ---------------------------------------------------------------------------
// CSR build
// ---------------------------------------------------------------------------
__global__ void zero_cnt_kernel() {
    int i = blockIdx.x * blockDim.x + threadIdx.x;
    if (i < N_TOT) g_cnt[i] = 0;
}

__global__ void hist_kernel(const int* __restrict__ edst) {
    int i = blockIdx.x * blockDim.x + threadIdx.x;
    if (i >= TOTAL_E) return;
    int et = i / N_EDGES;
    int d = __ldg(&edst[i]);
    atomicAdd(&g_cnt[et * N_NODES + d], 1);
}

__global__ __launch_bounds__(256) void scan_a_kernel() {
    __shared__ int s[256];
    const int tid = threadIdx.x;
    const int base = blockIdx.x * SCAN_CHUNK + tid * 8;
    int v[8];
    int tsum = 0;
#pragma unroll
    for (int k = 0; k < 8; k++) {
        int i = base + k;
        v[k] = (i < N_TOT) ? g_cnt[i] : 0;
        tsum += v[k];
    }
    s[tid] = tsum;
    __syncthreads();
    // Hillis-Steele inclusive scan over 256 thread sums
    for (int off = 1; off < 256; off <<= 1) {
        int t = (tid >= off) ? s[tid - off] : 0;
        __syncthreads();
        s[tid] += t;
        __syncthreads();
    }
    int run = s[tid] - tsum;   // exclusive prefix for this thread
#pragma unroll
    for (int k = 0; k < 8; k++) {
        int i = base + k;
        if (i < N_TOT) g_off[i] = run;
        run += v[k];
    }
    if (tid == 255) g_part[blockIdx.x] = s[255];
}

__global__ void scan_b_kernel() {
    if (threadIdx.x == 0 && blockIdx.x == 0) {
        int run = 0;
        for (int b = 0; b < SCAN_BLOCKS; b++) {
            int t = g_part[b];
            g_part[b] = run;
            run += t;
        }
        g_off[N_TOT] = run;    // == TOTAL_E
    }
}

__global__ void scan_c_kernel() {
    int i = blockIdx.x * blockDim.x + threadIdx.x;
    if (i >= N_TOT) return;
    int o = g_off[i] + g_part[i / SCAN_CHUNK];
    g_off[i] = o;
    g_pos[i] = o;
}

__global__ void fill_kernel(const int* __restrict__ esrc,
                            const int* __restrict__ edst) {
    int i = blockIdx.x * blockDim.x + threadIdx.x;
    if (i >= TOTAL_E) return;
    int et = i / N_EDGES;
    int d = __ldg(&edst[i]);
    int s = __ldg(&esrc[i]);
    int p = atomicAdd(&g_pos[et * N_NODES + d], 1);
    g_eidx[p] = s;
}

// ---------------------------------------------------------------------------
// Stage 1: Wh[e] = x @ W[e] via 3xTF32 mma.sync (fp32-accurate tensor GEMM).
// ---------------------------------------------------------------------------
__device__ __forceinline__ float tf32_rna(float x) {
    uint32_t u;
    asm("cvt.rna.tf32.f32 %0, %1;" : "=r"(u) : "f"(x));
    return __uint_as_float(u);
}

#define MMA_TF32(D, A, B)                                                     \
    asm volatile(                                                             \
        "mma.sync.aligned.m16n8k8.row.col.f32.tf32.tf32.f32 "                 \
        "{%0,%1,%2,%3}, {%4,%5,%6,%7}, {%8,%9}, {%0,%1,%2,%3};"               \
        : "+f"(D[0]), "+f"(D[1]), "+f"(D[2]), "+f"(D[3])                      \
        : "r"(A[0]), "r"(A[1]), "r"(A[2]), "r"(A[3]), "r"(B[0]), "r"(B[1]))

#define AS_STRIDE 20

__global__ __launch_bounds__(256, 1) void gemm_kernel(const float* __restrict__ x,
                                                      const float* __restrict__ W) {
    const int et = blockIdx.y;
    const int m0 = blockIdx.x * 128;
    const int tid = threadIdx.x;
    const int wid = tid >> 5;
    const int lane = tid & 31;
    const int m_off = (wid >> 1) * 32;
    const int n_off = (wid & 1) * 64;
    const int gq = lane >> 2;
    const int tg = lane & 3;

    __shared__ float As_hi[128 * AS_STRIDE];
    __shared__ float As_lo[128 * AS_STRIDE];
    __shared__ float Ws_hi[128 * AS_STRIDE];
    __shared__ float Ws_lo[128 * AS_STRIDE];

    const float* Wt = W + (size_t)et * IN_SIZE * OUT_SIZE;

    float acc[2][8][4];
#pragma unroll
    for (int i = 0; i < 2; i++)
#pragma unroll
        for (int j = 0; j < 8; j++)
#pragma unroll
            for (int c = 0; c < 4; c++) acc[i][j][c] = 0.0f;

    for (int k0 = 0; k0 < IN_SIZE; k0 += 16) {
#pragma unroll
        for (int i = 0; i < 2; i++) {
            int f4 = tid + i * 256;
            int row = f4 >> 2;
            int kc = (f4 & 3) * 4;
            int gm = m0 + row;
            float4 v = make_float4(0.f, 0.f, 0.f, 0.f);
            if (gm < N_NODES) v = *(const float4*)&x[(size_t)gm * IN_SIZE + k0 + kc];
            float4 h, l;
            h.x = tf32_rna(v.x); l.x = tf32_rna(v.x - h.x);
            h.y = tf32_rna(v.y); l.y = tf32_rna(v.y - h.y);
            h.z = tf32_rna(v.z); l.z = tf32_rna(v.z - h.z);
            h.w = tf32_rna(v.w); l.w = tf32_rna(v.w - h.w);
            *(float4*)&As_hi[row * AS_STRIDE + kc] = h;
            *(float4*)&As_lo[row * AS_STRIDE + kc] = l;
        }
#pragma unroll
        for (int i = 0; i < 2; i++) {
            int f4 = tid + i * 256;
            int kr = f4 >> 5;
            int nc = (f4 & 31) * 4;
            float4 v = *(const float4*)&Wt[(size_t)(k0 + kr) * OUT_SIZE + nc];
            float h, l;
            h = tf32_rna(v.x); l = tf32_rna(v.x - h);
            Ws_hi[(nc + 0) * AS_STRIDE + kr] = h; Ws_lo[(nc + 0) * AS_STRIDE + kr] = l;
            h = tf32_rna(v.y); l = tf32_rna(v.y - h);
            Ws_hi[(nc + 1) * AS_STRIDE + kr] = h; Ws_lo[(nc + 1) * AS_STRIDE + kr] = l;
            h = tf32_rna(v.z); l = tf32_rna(v.z - h);
            Ws_hi[(nc + 2) * AS_STRIDE + kr] = h; Ws_lo[(nc + 2) * AS_STRIDE + kr] = l;
            h = tf32_rna(v.w); l = tf32_rna(v.w - h);
            Ws_hi[(nc + 3) * AS_STRIDE + kr] = h; Ws_lo[(nc + 3) * AS_STRIDE + kr] = l;
        }
        __syncthreads();

#pragma unroll
        for (int ks = 0; ks < 16; ks += 8) {
            uint32_t ahi[2][4], alo[2][4];
#pragma unroll
            for (int mf = 0; mf < 2; mf++) {
                int r = m_off + mf * 16 + gq;
                int c = ks + tg;
                ahi[mf][0] = __float_as_uint(As_hi[r * AS_STRIDE + c]);
                ahi[mf][1] = __float_as_uint(As_hi[(r + 8) * AS_STRIDE + c]);
                ahi[mf][2] = __float_as_uint(As_hi[r * AS_STRIDE + c + 4]);
                ahi[mf][3] = __float_as_uint(As_hi[(r + 8) * AS_STRIDE + c + 4]);
                alo[mf][0] = __float_as_uint(As_lo[r * AS_STRIDE + c]);
                alo[mf][1] = __float_as_uint(As_lo[(r + 8) * AS_STRIDE + c]);
                alo[mf][2] = __float_as_uint(As_lo[r * AS_STRIDE + c + 4]);
                alo[mf][3] = __float_as_uint(As_lo[(r + 8) * AS_STRIDE + c + 4]);
            }
#pragma unroll
            for (int nf = 0; nf < 8; nf++) {
                uint32_t bhi[2], blo[2];
                int n = n_off + nf * 8 + gq;
                int c = ks + tg;
                bhi[0] = __float_as_uint(Ws_hi[n * AS_STRIDE + c]);
                bhi[1] = __float_as_uint(Ws_hi[n * AS_STRIDE + c + 4]);
                blo[0] = __float_as_uint(Ws_lo[n * AS_STRIDE + c]);
                blo[1] = __float_as_uint(Ws_lo[n * AS_STRIDE + c + 4]);
#pragma unroll
                for (int mf = 0; mf < 2; mf++) {
                    MMA_TF32(acc[mf][nf], ahi[mf], bhi);
                    MMA_TF32(acc[mf][nf], ahi[mf], blo);
                    MMA_TF32(acc[mf][nf], alo[mf], bhi);
                }
            }
        }
        __syncthreads();
    }

    float* dst = g_Wh + (size_t)et * N_NODES * OUT_SIZE;
#pragma unroll
    for (int mf = 0; mf < 2; mf++) {
#pragma unroll
        for (int nf = 0; nf < 8; nf++) {
            int row = m0 + m_off + mf * 16 + gq;
            int col = n_off + nf * 8 + tg * 2;
            if (row < N_NODES) {
                *(float2*)&dst[(size_t)row * OUT_SIZE + col] =
                    make_float2(acc[mf][nf][0], acc[mf][nf][1]);
            }
            if (row + 8 < N_NODES) {
                *(float2*)&dst[(size_t)(row + 8) * OUT_SIZE + col] =
                    make_float2(acc[mf][nf][2], acc[mf][nf][3]);
            }
        }
    }
}

// ---------------------------------------------------------------------------
// Stage 2: atomic-free gather + mean + bias, writes final output.
// One warp per (node, etype); lane owns 4 contiguous channels.
// ---------------------------------------------------------------------------
__global__ __launch_bounds__(256) void gather_kernel(float* __restrict__ out,
                                                     const float* __restrict__ b) {
    const int et = blockIdx.y;
    const int wid = threadIdx.x >> 5;
    const int lane = threadIdx.x & 31;
    const int n = blockIdx.x * 8 + wid;
    if (n >= N_NODES) return;

    const int base = et * N_NODES + n;
    const int beg = __ldg(&g_off[base]);
    const int end = __ldg(&g_off[base + 1]);

    const float* wh = g_Wh + (size_t)et * N_NODES * OUT_SIZE;
    float4 acc = make_float4(0.f, 0.f, 0.f, 0.f);

    int j = beg;
    for (; j + 4 <= end; j += 4) {
        int s0 = __ldg(&g_eidx[j + 0]);
        int s1 = __ldg(&g_eidx[j + 1]);
        int s2 = __ldg(&g_eidx[j + 2]);
        int s3 = __ldg(&g_eidx[j + 3]);
        float4 v0 = __ldg((const float4*)&wh[(size_t)s0 * OUT_SIZE + lane * 4]);
        float4 v1 = __ldg((const float4*)&wh[(size_t)s1 * OUT_SIZE + lane * 4]);
        float4 v2 = __ldg((const float4*)&wh[(size_t)s2 * OUT_SIZE + lane * 4]);
        float4 v3 = __ldg((const float4*)&wh[(size_t)s3 * OUT_SIZE + lane * 4]);
        acc.x += v0.x + v1.x + v2.x + v3.x;
        acc.y += v0.y + v1.y + v2.y + v3.y;
        acc.z += v0.z + v1.z + v2.z + v3.z;
        acc.w += v0.w + v1.w + v2.w + v3.w;
    }
    for (; j < end; j++) {
        int s = __ldg(&g_eidx[j]);
        float4 v = __ldg((const float4*)&wh[(size_t)s * OUT_SIZE + lane * 4]);
        acc.x += v.x; acc.y += v.y; acc.z += v.z; acc.w += v.w;
    }

    float4 r;
    int cnt = end - beg;
    if (cnt > 0) {
        float inv = 1.0f / (float)cnt;
        float4 bb = __ldg(&((const float4*)b)[et * 32 + lane]);
        r.x = acc.x * inv + bb.x;
        r.y = acc.y * inv + bb.y;
        r.z = acc.z * inv + bb.z;
        r.w = acc.w * inv + bb.w;
    } else {
        r = make_float4(0.f, 0.f, 0.f, 0.f);
    }
    ((float4*)out)[((size_t)n * N_ET + et) * 32 + lane] = r;
}

// ---------------------------------------------------------------------------
extern "C" void kernel_launch(void* const* d_in, const int* in_sizes, int n_in,
                              void* d_out, int out_size) {
    const float* x    = (const float*)d_in[0];
    const int*   esrc = (const int*)d_in[1];
    const int*   edst = (const int*)d_in[2];
    const float* W    = (const float*)d_in[3];
    const float* b    = (const float*)d_in[4];
    float* out = (float*)d_out;

    // CSR build
    zero_cnt_kernel<<<(N_TOT + 255) / 256, 256>>>();
    hist_kernel<<<(TOTAL_E + 255) / 256, 256>>>(edst);
    scan_a_kernel<<<SCAN_BLOCKS, 256>>>();
    scan_b_kernel<<<1, 32>>>();
    scan_c_kernel<<<(N_TOT + 255) / 256, 256>>>();
    fill_kernel<<<(TOTAL_E + 255) / 256, 256>>>(esrc, edst);

    // GEMM
    dim3 ggrid((N_NODES + 127) / 128, N_ET);
    gemm_kernel<<<ggrid, 256>>>(x, W);

    // Gather + mean + bias (writes final output, covers every element)
    dim3 agrid((N_NODES + 7) / 8, N_ET);
    gather_kernel<<<agrid, 256>>>(out, b);
}